// round 13
// baseline (speedup 1.0000x reference)
#include <cuda_runtime.h>
#include <cuda_fp16.h>

// LBP uniform (P=8, R=1) over (B,C,H,W)=(32,3,512,512) float32.
// R13 = R12 (2 output rows/warp, pipelined coalesced chunks, exact f16x2
// compares, f32x2 packed scaling) + register diet for occupancy:
//  - __launch_bounds__(256,6): 40-reg cap -> 6 CTAs/SM (occ 75% theoretical)
//  - immediate float2 stores per pixel-pair (no res[4] accumulation)
//  - hfma2 weight constants inlined (immediate forms, not live registers)

#define IMG_W 512
#define IMG_H 512
#define FULL 0xFFFFFFFFu

__device__ __forceinline__ unsigned prmt(unsigned a, unsigned b, unsigned sel) {
    unsigned d;
    asm("prmt.b32 %0, %1, %2, %3;" : "=r"(d) : "r"(a), "r"(b), "r"(sel));
    return d;
}

// two packed floats (lo,hi) * 255 -> f16x2 (RZ). Exact: RN f32 mul then RZ.
__device__ __forceinline__ unsigned conv2(unsigned long long px2) {
    unsigned d;
    asm("{\n\t"
        ".reg .b64 t;\n\t"
        ".reg .f32 lo, hi;\n\t"
        "mul.rn.f32x2 t, %1, %2;\n\t"
        "mov.b64 {lo, hi}, t;\n\t"
        "cvt.rz.f16x2.f32 %0, hi, lo;\n\t"
        "}"
        : "=r"(d) : "l"(px2), "l"(0x437F0000437F0000ull));  // 255.0f x2
    return d;
}

__device__ __forceinline__ __half2 u2h(unsigned x) {
    __half2 h;
    *reinterpret_cast<unsigned*>(&h) = x;
    return h;
}

// weighted accumulate: m += (a >= c) * W   (W = compile-time half2 constant)
#define ACC(mreg, aval, cval, Wbits) \
    mreg = __hfma2(__hge2(u2h(aval), cval), u2h(Wbits##u), mreg)

__device__ __forceinline__ float lbp_tail(unsigned m) {
    const unsigned mm  = m * 0x101u;          // m | m<<8
    const unsigned rot = (mm >> 7) & 0xFFu;   // circular rot-left-1
    const int trans = __popc(m ^ rot);
    const int ones  = __popc(m);
    return (float)((trans <= 2) ? ones : 9) * (1.0f / 255.0f);
}

// load one chunk (4 px) of one row, convert to two f16x2 words
__device__ __forceinline__ void load4(const float* p, unsigned& w0, unsigned& w1) {
    const ulonglong2 u = *reinterpret_cast<const ulonglong2*>(p);
    w0 = conv2(u.x);
    w1 = conv2(u.y);
}

__global__ __launch_bounds__(256, 6)
void lbp_kernel(const float* __restrict__ x, float* __restrict__ out, int npairs) {
    const int pr   = blockIdx.x * (blockDim.x >> 5) + (threadIdx.x >> 5);
    const int lane = threadIdx.x & 31;
    if (pr >= npairs) return;

    const int r0 = pr * 2;                 // even; pair stays inside one image
    const int h0 = r0 & (IMG_H - 1);
    const bool hasTop = (h0 != 0);
    const bool hasBot = (h0 != IMG_H - 2);

    const float* rb = x + (size_t)r0 * IMG_W + lane * 4;   // row r0
    const float* ra = rb - IMG_W;                           // row r0-1
    const float* rc = rb + IMG_W;                           // row r0+1
    const float* rd = rb + 2 * IMG_W;                       // row r0+2
    float* op0 = out + (size_t)r0 * IMG_W + lane * 4;
    float* op1 = op0 + IMG_W;

    const int upLane = (lane + 31) & 31;
    const int dnLane = (lane + 1) & 31;

    // prev-chunk edge words (word[1]) per row; 0 at left image border
    unsigned pa1 = 0u, pb1 = 0u, pc1 = 0u, pd1 = 0u;
    // current chunk: rows a (top), b (=r0), c (=r1), d (bottom)
    unsigned a0, a1, b0, b1, c0, c1, d0, d1;
    if (hasTop) load4(ra, a0, a1); else { a0 = 0u; a1 = 0u; }
    load4(rb, b0, b1);
    load4(rc, c0, c1);
    if (hasBot) load4(rd, d0, d1); else { d0 = 0u; d1 = 0u; }

#pragma unroll
    for (int k = 0; k < 4; k++) {
        // lookahead: next chunk
        unsigned na0 = 0u, na1 = 0u, nb0 = 0u, nb1 = 0u;
        unsigned nc0 = 0u, nc1 = 0u, nd0 = 0u, nd1 = 0u;
        if (k < 3) {
            const int off = 128 * (k + 1);
            if (hasTop) load4(ra + off, na0, na1);
            load4(rb + off, nb0, nb1);
            load4(rc + off, nc0, nc1);
            if (hasBot) load4(rd + off, nd0, nd1);
        }

        // halos: left = word1 of lane-1 (lane0 <- lane31's prev chunk);
        //        right = word0 of lane+1 (lane31 <- lane0's next chunk)
        unsigned ls, rs;
        ls = (lane == 31) ? pa1 : a1;  const unsigned aal = __shfl_sync(FULL, ls, upLane);
        rs = (lane == 0)  ? na0 : a0;  const unsigned aar = __shfl_sync(FULL, rs, dnLane);
        ls = (lane == 31) ? pb1 : b1;  const unsigned bal = __shfl_sync(FULL, ls, upLane);
        rs = (lane == 0)  ? nb0 : b0;  const unsigned bar = __shfl_sync(FULL, rs, dnLane);
        ls = (lane == 31) ? pc1 : c1;  const unsigned cal = __shfl_sync(FULL, ls, upLane);
        rs = (lane == 0)  ? nc0 : c0;  const unsigned car = __shfl_sync(FULL, rs, dnLane);
        ls = (lane == 31) ? pd1 : d1;  const unsigned dal = __shfl_sync(FULL, ls, upLane);
        rs = (lane == 0)  ? nd0 : d0;  const unsigned dar = __shfl_sync(FULL, rs, dnLane);

        // shifted windows per row: m=(px-1,px0) mid=(px1,px2) p=(px3,px4)
        const unsigned am = prmt(aal, a0, 0x5432u), amid = prmt(a0, a1, 0x5432u), ap = prmt(a1, aar, 0x5432u);
        const unsigned bm = prmt(bal, b0, 0x5432u), bmid = prmt(b0, b1, 0x5432u), bp = prmt(b1, bar, 0x5432u);
        const unsigned cm = prmt(cal, c0, 0x5432u), cmid = prmt(c0, c1, 0x5432u), cp = prmt(c1, car, 0x5432u);
        const unsigned dm = prmt(dal, d0, 0x5432u), dmid = prmt(d0, d1, 0x5432u), dp = prmt(d1, dar, 0x5432u);

#pragma unroll
        for (int p = 0; p < 2; p++) {
            // output row 0: top=a, center=b, bottom=c
            const __half2 fc0 = h2floor(u2h(p ? b1 : b0));
            // output row 1: top=b, center=c, bottom=d
            const __half2 fc1 = h2floor(u2h(p ? c1 : c0));

            const unsigned tl0 = p ? amid : am, tc0 = p ? a1 : a0, tr0 = p ? ap : amid;
            const unsigned cl0 = p ? bmid : bm, cr0 = p ? bp : bmid;
            const unsigned bl0 = p ? cmid : cm, bc0 = p ? c1 : c0, br0 = p ? cp : cmid;

            const unsigned tl1 = p ? bmid : bm, tc1 = p ? b1 : b0, tr1 = p ? bp : bmid;
            const unsigned cl1 = p ? cmid : cm, cr1 = p ? cp : cmid;
            const unsigned bl1 = p ? dmid : dm, bc1 = p ? d1 : d0, br1 = p ? dp : dmid;

            // two independent weighted chains (circular order: tl,t,tr,r,br,b,bl,l)
            __half2 m0 = __hge2(u2h(tl0), fc0);
            __half2 m1 = __hge2(u2h(tl1), fc1);
            ACC(m0, tc0, fc0, 0x40004000);  ACC(m1, tc1, fc1, 0x40004000);  // *2
            ACC(m0, tr0, fc0, 0x44004400);  ACC(m1, tr1, fc1, 0x44004400);  // *4
            ACC(m0, cr0, fc0, 0x48004800);  ACC(m1, cr1, fc1, 0x48004800);  // *8
            ACC(m0, br0, fc0, 0x4C004C00);  ACC(m1, br1, fc1, 0x4C004C00);  // *16
            ACC(m0, bc0, fc0, 0x50005000);  ACC(m1, bc1, fc1, 0x50005000);  // *32
            ACC(m0, bl0, fc0, 0x54005400);  ACC(m1, bl1, fc1, 0x54005400);  // *64
            ACC(m0, cl0, fc0, 0x58005800);  ACC(m1, cl1, fc1, 0x58005800);  // *128

            // immediate float2 stores (frees result registers early)
            float2 r0v, r1v;
            r0v.x = lbp_tail((unsigned)__half2int_rz(__low2half(m0)));
            r0v.y = lbp_tail((unsigned)__half2int_rz(__high2half(m0)));
            r1v.x = lbp_tail((unsigned)__half2int_rz(__low2half(m1)));
            r1v.y = lbp_tail((unsigned)__half2int_rz(__high2half(m1)));
            *reinterpret_cast<float2*>(op0 + 128 * k + 2 * p) = r0v;
            *reinterpret_cast<float2*>(op1 + 128 * k + 2 * p) = r1v;
        }

        // rotate pipeline state
        pa1 = a1; pb1 = b1; pc1 = c1; pd1 = d1;
        a0 = na0; a1 = na1; b0 = nb0; b1 = nb1;
        c0 = nc0; c1 = nc1; d0 = nd0; d1 = nd1;
    }
}

extern "C" void kernel_launch(void* const* d_in, const int* in_sizes, int n_in,
                              void* d_out, int out_size) {
    const float* x = (const float*)d_in[0];
    float* out = (float*)d_out;
    const int nrows  = out_size / IMG_W;   // B*C*H = 49152
    const int npairs = nrows / 2;          // 24576 warps, 1 row-pair/warp
    const int threads = 256;               // 8 warps/block
    const int blocks = (npairs + 7) / 8;
    lbp_kernel<<<blocks, threads>>>(x, out, npairs);
}

// round 14
// speedup vs baseline: 1.1616x; 1.1616x over previous
#include <cuda_runtime.h>
#include <cuda_fp16.h>

// LBP uniform (P=8, R=1) over (B,C,H,W)=(32,3,512,512) float32.
// R14 = R12 exactly (2 output rows/warp, pipelined coalesced chunks, exact
// f16x2 compares, f32x2 packed scaling, float4 STG.128 stores) + register
// diet WITHOUT touching the store path:
//  - hfma2 weight constants as compile-time immediates (frees ~7 regs)
//  - __launch_bounds__(256,6): target 40 regs -> 6 CTAs/SM (75% occ theor.)
// R13 showed float2 stores double L2 store traffic -> keep STG.128.

#define IMG_W 512
#define IMG_H 512
#define FULL 0xFFFFFFFFu

__device__ __forceinline__ unsigned prmt(unsigned a, unsigned b, unsigned sel) {
    unsigned d;
    asm("prmt.b32 %0, %1, %2, %3;" : "=r"(d) : "r"(a), "r"(b), "r"(sel));
    return d;
}

// two packed floats (lo,hi) * 255 -> f16x2 (RZ). Exact: RN f32 mul then RZ.
__device__ __forceinline__ unsigned conv2(unsigned long long px2) {
    unsigned d;
    asm("{\n\t"
        ".reg .b64 t;\n\t"
        ".reg .f32 lo, hi;\n\t"
        "mul.rn.f32x2 t, %1, %2;\n\t"
        "mov.b64 {lo, hi}, t;\n\t"
        "cvt.rz.f16x2.f32 %0, hi, lo;\n\t"
        "}"
        : "=r"(d) : "l"(px2), "l"(0x437F0000437F0000ull));  // 255.0f x2
    return d;
}

__device__ __forceinline__ __half2 u2h(unsigned x) {
    __half2 h;
    *reinterpret_cast<unsigned*>(&h) = x;
    return h;
}

// weighted accumulate: m += (a >= c) * W   (W = compile-time half2 constant)
#define ACC(mreg, aval, cval, Wbits) \
    mreg = __hfma2(__hge2(u2h(aval), cval), u2h(Wbits##u), mreg)

__device__ __forceinline__ float lbp_tail(unsigned m) {
    const unsigned mm  = m * 0x101u;          // m | m<<8
    const unsigned rot = (mm >> 7) & 0xFFu;   // circular rot-left-1
    const int trans = __popc(m ^ rot);
    const int ones  = __popc(m);
    return (float)((trans <= 2) ? ones : 9) * (1.0f / 255.0f);
}

// load one chunk (4 px) of one row, convert to two f16x2 words
__device__ __forceinline__ void load4(const float* p, unsigned& w0, unsigned& w1) {
    const ulonglong2 u = *reinterpret_cast<const ulonglong2*>(p);
    w0 = conv2(u.x);
    w1 = conv2(u.y);
}

__global__ __launch_bounds__(256, 6)
void lbp_kernel(const float* __restrict__ x, float* __restrict__ out, int npairs) {
    const int pr   = blockIdx.x * (blockDim.x >> 5) + (threadIdx.x >> 5);
    const int lane = threadIdx.x & 31;
    if (pr >= npairs) return;

    const int r0 = pr * 2;                 // even; pair stays inside one image
    const int h0 = r0 & (IMG_H - 1);
    const bool hasTop = (h0 != 0);
    const bool hasBot = (h0 != IMG_H - 2);

    const float* rb = x + (size_t)r0 * IMG_W + lane * 4;   // row r0
    const float* ra = rb - IMG_W;                           // row r0-1
    const float* rc = rb + IMG_W;                           // row r0+1
    const float* rd = rb + 2 * IMG_W;                       // row r0+2
    float* op0 = out + (size_t)r0 * IMG_W + lane * 4;
    float* op1 = op0 + IMG_W;

    const int upLane = (lane + 31) & 31;
    const int dnLane = (lane + 1) & 31;

    // prev-chunk edge words (word[1]) per row; 0 at left image border
    unsigned pa1 = 0u, pb1 = 0u, pc1 = 0u, pd1 = 0u;
    // current chunk: rows a (top), b (=r0), c (=r1), d (bottom)
    unsigned a0, a1, b0, b1, c0, c1, d0, d1;
    if (hasTop) load4(ra, a0, a1); else { a0 = 0u; a1 = 0u; }
    load4(rb, b0, b1);
    load4(rc, c0, c1);
    if (hasBot) load4(rd, d0, d1); else { d0 = 0u; d1 = 0u; }

#pragma unroll
    for (int k = 0; k < 4; k++) {
        // lookahead: next chunk
        unsigned na0 = 0u, na1 = 0u, nb0 = 0u, nb1 = 0u;
        unsigned nc0 = 0u, nc1 = 0u, nd0 = 0u, nd1 = 0u;
        if (k < 3) {
            const int off = 128 * (k + 1);
            if (hasTop) load4(ra + off, na0, na1);
            load4(rb + off, nb0, nb1);
            load4(rc + off, nc0, nc1);
            if (hasBot) load4(rd + off, nd0, nd1);
        }

        // halos: left = word1 of lane-1 (lane0 <- lane31's prev chunk);
        //        right = word0 of lane+1 (lane31 <- lane0's next chunk)
        unsigned ls, rs;
        ls = (lane == 31) ? pa1 : a1;  const unsigned aal = __shfl_sync(FULL, ls, upLane);
        rs = (lane == 0)  ? na0 : a0;  const unsigned aar = __shfl_sync(FULL, rs, dnLane);
        ls = (lane == 31) ? pb1 : b1;  const unsigned bal = __shfl_sync(FULL, ls, upLane);
        rs = (lane == 0)  ? nb0 : b0;  const unsigned bar = __shfl_sync(FULL, rs, dnLane);
        ls = (lane == 31) ? pc1 : c1;  const unsigned cal = __shfl_sync(FULL, ls, upLane);
        rs = (lane == 0)  ? nc0 : c0;  const unsigned car = __shfl_sync(FULL, rs, dnLane);
        ls = (lane == 31) ? pd1 : d1;  const unsigned dal = __shfl_sync(FULL, ls, upLane);
        rs = (lane == 0)  ? nd0 : d0;  const unsigned dar = __shfl_sync(FULL, rs, dnLane);

        // shifted windows per row: m=(px-1,px0) mid=(px1,px2) p=(px3,px4)
        const unsigned am = prmt(aal, a0, 0x5432u), amid = prmt(a0, a1, 0x5432u), ap = prmt(a1, aar, 0x5432u);
        const unsigned bm = prmt(bal, b0, 0x5432u), bmid = prmt(b0, b1, 0x5432u), bp = prmt(b1, bar, 0x5432u);
        const unsigned cm = prmt(cal, c0, 0x5432u), cmid = prmt(c0, c1, 0x5432u), cp = prmt(c1, car, 0x5432u);
        const unsigned dm = prmt(dal, d0, 0x5432u), dmid = prmt(d0, d1, 0x5432u), dp = prmt(d1, dar, 0x5432u);

        float res0[4], res1[4];
#pragma unroll
        for (int p = 0; p < 2; p++) {
            // output row 0: top=a, center=b, bottom=c
            const __half2 fc0 = h2floor(u2h(p ? b1 : b0));
            // output row 1: top=b, center=c, bottom=d
            const __half2 fc1 = h2floor(u2h(p ? c1 : c0));

            const unsigned tl0 = p ? amid : am, tc0 = p ? a1 : a0, tr0 = p ? ap : amid;
            const unsigned cl0 = p ? bmid : bm, cr0 = p ? bp : bmid;
            const unsigned bl0 = p ? cmid : cm, bc0 = p ? c1 : c0, br0 = p ? cp : cmid;

            const unsigned tl1 = p ? bmid : bm, tc1 = p ? b1 : b0, tr1 = p ? bp : bmid;
            const unsigned cl1 = p ? cmid : cm, cr1 = p ? cp : cmid;
            const unsigned bl1 = p ? dmid : dm, bc1 = p ? d1 : d0, br1 = p ? dp : dmid;

            // two independent weighted chains (circular order: tl,t,tr,r,br,b,bl,l)
            __half2 m0 = __hge2(u2h(tl0), fc0);
            __half2 m1 = __hge2(u2h(tl1), fc1);
            ACC(m0, tc0, fc0, 0x40004000);  ACC(m1, tc1, fc1, 0x40004000);  // *2
            ACC(m0, tr0, fc0, 0x44004400);  ACC(m1, tr1, fc1, 0x44004400);  // *4
            ACC(m0, cr0, fc0, 0x48004800);  ACC(m1, cr1, fc1, 0x48004800);  // *8
            ACC(m0, br0, fc0, 0x4C004C00);  ACC(m1, br1, fc1, 0x4C004C00);  // *16
            ACC(m0, bc0, fc0, 0x50005000);  ACC(m1, bc1, fc1, 0x50005000);  // *32
            ACC(m0, bl0, fc0, 0x54005400);  ACC(m1, bl1, fc1, 0x54005400);  // *64
            ACC(m0, cl0, fc0, 0x58005800);  ACC(m1, cl1, fc1, 0x58005800);  // *128

            res0[2 * p]     = lbp_tail((unsigned)__half2int_rz(__low2half(m0)));
            res0[2 * p + 1] = lbp_tail((unsigned)__half2int_rz(__high2half(m0)));
            res1[2 * p]     = lbp_tail((unsigned)__half2int_rz(__low2half(m1)));
            res1[2 * p + 1] = lbp_tail((unsigned)__half2int_rz(__high2half(m1)));
        }
        *reinterpret_cast<float4*>(op0 + 128 * k) = make_float4(res0[0], res0[1], res0[2], res0[3]);
        *reinterpret_cast<float4*>(op1 + 128 * k) = make_float4(res1[0], res1[1], res1[2], res1[3]);

        // rotate pipeline state
        pa1 = a1; pb1 = b1; pc1 = c1; pd1 = d1;
        a0 = na0; a1 = na1; b0 = nb0; b1 = nb1;
        c0 = nc0; c1 = nc1; d0 = nd0; d1 = nd1;
    }
}

extern "C" void kernel_launch(void* const* d_in, const int* in_sizes, int n_in,
                              void* d_out, int out_size) {
    const float* x = (const float*)d_in[0];
    float* out = (float*)d_out;
    const int nrows  = out_size / IMG_W;   // B*C*H = 49152
    const int npairs = nrows / 2;          // 24576 warps, 1 row-pair/warp
    const int threads = 256;               // 8 warps/block
    const int blocks = (npairs + 7) / 8;
    lbp_kernel<<<blocks, threads>>>(x, out, npairs);
}